// round 9
// baseline (speedup 1.0000x reference)
#include <cuda_runtime.h>
#include <math.h>

// ---------------- problem constants ----------------
#define B_    512
#define CIN   12
#define LIN   5000
#define CO1   32
#define KS1   50
#define ST1   10
#define L1    496      // (5000-50)/10+1
#define NF    32
#define KS2   25
#define ST2   5
#define T_    95       // (496-25)/5+1
#define LAT   32
#define HID   64
#define EPSC  1e-5f

typedef unsigned long long ull;

// ---- f32x2 helpers (sm_103a packed fp32 path) ----
__device__ __forceinline__ ull ldp(const float* p) {           // 8B-aligned pair load
    return *reinterpret_cast<const ull*>(p);
}
__device__ __forceinline__ ull mkp(float lo, float hi) {
    ull r; asm("mov.b64 %0, {%1, %2};" : "=l"(r) : "f"(lo), "f"(hi)); return r;
}
__device__ __forceinline__ void fma2(ull& acc, ull a, ull b) {
    asm("fma.rn.f32x2 %0, %1, %2, %0;" : "+l"(acc) : "l"(a), "l"(b));
}
__device__ __forceinline__ float red2(ull a) {
    float lo, hi;
    asm("mov.b64 {%0, %1}, %2;" : "=f"(lo), "=f"(hi) : "l"(a));
    return lo + hi;
}

// ---------------- scratch (device globals; no allocation allowed) ----------------
__device__ float g_y1[B_ * CO1 * L1];   // conv1 output [b][co][l]
__device__ float g_y2[B_ * NF * T_];    // conv2 output [b][co][t]
__device__ float g_xt[B_ * T_ * LAT];   // hoisted LN(proj) [b][t][l]
__device__ float g_part[2][32][16];     // [sum|sumsq][ch][chunk]
__device__ float g_scale1[32], g_shift1[32];
__device__ float g_scale2[32], g_shift2[32];

// ======================================================================
// K1: conv1 + bias.  Block = (b, 124-wide l chunk).  Thread tile 4co x 4l.
// k paired (25 pairs): LDS.64 x/w + fma.rn.f32x2 accumulate.
// SW1_STRIDE even (602) so every co row is 8B-aligned (2-way bank on w ok).
// ======================================================================
#define LBLK 124
#define SX_STRIDE 1284     // 124*10+40 = 1280, +4 pad (even)
#define SW1_STRIDE 602     // 600 + 2 pad (even, 8B-aligned rows)

__global__ __launch_bounds__(256, 1)
void conv1_kernel(const float* __restrict__ x, const float* __restrict__ w,
                  const float* __restrict__ bias) {
    extern __shared__ float smem[];
    float* sx = smem;                        // CIN * SX_STRIDE
    float* sw = smem + CIN * SX_STRIDE;      // CO1 * SW1_STRIDE

    const int b     = blockIdx.x >> 2;
    const int chunk = blockIdx.x & 3;
    const int l0    = chunk * LBLK;
    const int tid   = threadIdx.x;

    for (int i = tid; i < CO1 * CIN * KS1; i += 256) {
        int co = i / (CIN * KS1), r = i % (CIN * KS1);
        sw[co * SW1_STRIDE + r] = w[i];
    }
    const int xbase = b * CIN * LIN + l0 * ST1;
    for (int i = tid; i < CIN * 1280; i += 256) {
        int ci = i / 1280, p = i % 1280;
        sx[ci * SX_STRIDE + p] = x[xbase + ci * LIN + p];
    }
    __syncthreads();

    if (tid >= 248) return;                  // 8 co-tiles * 31 l-tiles
    const int co0 = (tid & 7) * 4;
    const int lt  = (tid >> 3) * 4;          // 0..120

    ull a00=0,a01=0,a02=0,a03=0, a10=0,a11=0,a12=0,a13=0;
    ull a20=0,a21=0,a22=0,a23=0, a30=0,a31=0,a32=0,a33=0;

    for (int ci = 0; ci < CIN; ci++) {
        const float* sxp = sx + ci * SX_STRIDE + lt * ST1;   // even base
        const float* swp = sw + co0 * SW1_STRIDE + ci * KS1; // even base
        #pragma unroll 5
        for (int kp = 0; kp < 25; kp++) {
            const int k = kp * 2;
            ull x0 = ldp(sxp + k);
            ull x1 = ldp(sxp + k + 10);
            ull x2 = ldp(sxp + k + 20);
            ull x3 = ldp(sxp + k + 30);
            ull w0 = ldp(swp + k);
            ull w1 = ldp(swp + SW1_STRIDE + k);
            ull w2 = ldp(swp + 2 * SW1_STRIDE + k);
            ull w3 = ldp(swp + 3 * SW1_STRIDE + k);
            fma2(a00, w0, x0); fma2(a01, w0, x1); fma2(a02, w0, x2); fma2(a03, w0, x3);
            fma2(a10, w1, x0); fma2(a11, w1, x1); fma2(a12, w1, x2); fma2(a13, w1, x3);
            fma2(a20, w2, x0); fma2(a21, w2, x1); fma2(a22, w2, x2); fma2(a23, w2, x3);
            fma2(a30, w3, x0); fma2(a31, w3, x1); fma2(a32, w3, x2); fma2(a33, w3, x3);
        }
    }

    float* yp = g_y1 + (b * CO1 + co0) * L1 + l0 + lt;
    float b0 = bias[co0], b1 = bias[co0+1], b2 = bias[co0+2], b3 = bias[co0+3];
    yp[0]=red2(a00)+b0; yp[1]=red2(a01)+b0; yp[2]=red2(a02)+b0; yp[3]=red2(a03)+b0; yp+=L1;
    yp[0]=red2(a10)+b1; yp[1]=red2(a11)+b1; yp[2]=red2(a12)+b1; yp[3]=red2(a13)+b1; yp+=L1;
    yp[0]=red2(a20)+b2; yp[1]=red2(a21)+b2; yp[2]=red2(a22)+b2; yp[3]=red2(a23)+b2; yp+=L1;
    yp[0]=red2(a30)+b3; yp[1]=red2(a31)+b3; yp[2]=red2(a32)+b3; yp[3]=red2(a33)+b3;
}

// ======================================================================
// BN stats: deterministic two-pass tree reduction (no float atomics).
// ======================================================================
__global__ __launch_bounds__(256, 4)
void bn_stats_kernel(int which) {
    const float* y  = which ? g_y2 : g_y1;
    const int perB  = which ? T_ : L1;
    const int ch    = blockIdx.x;
    const int chunk = blockIdx.y;
    const int b0    = chunk * 32;
    const int tid   = threadIdx.x;
    const int n     = 32 * perB;

    float s = 0.f, sq = 0.f;
    for (int i = tid; i < n; i += 256) {
        int b = b0 + i / perB, p = i % perB;
        float v = y[(b * 32 + ch) * perB + p];
        s += v; sq += v * v;
    }
    __shared__ float rs[256], rq[256];
    rs[tid] = s; rq[tid] = sq;
    __syncthreads();
    for (int off = 128; off > 0; off >>= 1) {
        if (tid < off) { rs[tid] += rs[tid + off]; rq[tid] += rq[tid + off]; }
        __syncthreads();
    }
    if (tid == 0) {
        g_part[0][ch][chunk] = rs[0];
        g_part[1][ch][chunk] = rq[0];
    }
}

__global__ void bn_final_kernel(const float* __restrict__ g, const float* __restrict__ bb,
                                int which) {
    int ch = threadIdx.x;   // 32 threads
    float invN = which ? (1.f / (B_ * (float)T_)) : (1.f / (B_ * (float)L1));
    float s = 0.f, sq = 0.f;
    for (int c = 0; c < 16; c++) { s += g_part[0][ch][c]; sq += g_part[1][ch][c]; }
    float m  = s * invN;
    float v  = sq * invN - m * m;
    float sc = g[ch] * rsqrtf(v + EPSC);
    if (which) { g_scale2[ch] = sc; g_shift2[ch] = bb[ch] - m * sc; }
    else       { g_scale1[ch] = sc; g_shift1[ch] = bb[ch] - m * sc; }
}

// ======================================================================
// K3: conv2 + bias, BN1 affine + ReLU fused on input.
// Weights relaid [co][ci*26 + k] with zero tap at k=25 -> 13 clean k-pairs.
// w via LDS.64 (even 834 stride); x via 2x LDS.32 + pack (t offsets odd).
// ======================================================================
#define SH_STRIDE  498     // 496 + 2 pad (even)
#define SW2_STRIDE 834     // 32*26 + 2 pad (even)

__global__ __launch_bounds__(256, 1)
void conv2_kernel(const float* __restrict__ w2, const float* __restrict__ c2b) {
    extern __shared__ float smem[];
    float* sh = smem;                       // NF * SH_STRIDE
    float* sw = smem + NF * SH_STRIDE;      // NF * SW2_STRIDE

    const int b   = blockIdx.x;
    const int tid = threadIdx.x;

    for (int i = tid; i < NF * NF * KS2; i += 256) {   // 25600
        int co = i / (NF * KS2), r = i % (NF * KS2);
        int ci = r / KS2, k = r % KS2;
        sw[co * SW2_STRIDE + ci * 26 + k] = w2[i];
    }
    for (int i = tid; i < NF * NF; i += 256) {          // zero tap k=25
        sw[(i >> 5) * SW2_STRIDE + (i & 31) * 26 + 25] = 0.f;
    }
    for (int i = tid; i < NF * L1; i += 256) {
        int ci = i / L1, p = i % L1;
        float v = g_scale1[ci] * g_y1[(b * NF) * L1 + i] + g_shift1[ci];
        sh[ci * SH_STRIDE + p] = fmaxf(v, 0.f);
    }
    __syncthreads();

    const int co0 = (tid & 7) * 4;
    const int tt  = tid >> 3;
    if (tt >= 24) return;
    const int t0 = tt * 4;

    ull a00=0,a01=0,a02=0,a03=0, a10=0,a11=0,a12=0,a13=0;
    ull a20=0,a21=0,a22=0,a23=0, a30=0,a31=0,a32=0,a33=0;

    for (int ci = 0; ci < NF; ci++) {
        const float* shp = sh + ci * SH_STRIDE + t0 * ST2;
        const float* swp = sw + co0 * SW2_STRIDE + ci * 26;
        #pragma unroll
        for (int kp = 0; kp < 13; kp++) {
            const int k = kp * 2;
            ull x0 = mkp(shp[k],      shp[k + 1]);
            ull x1 = mkp(shp[k + 5],  shp[k + 6]);
            ull x2 = mkp(shp[k + 10], shp[k + 11]);
            ull x3 = mkp(shp[k + 15], shp[k + 16]);
            ull w0 = ldp(swp + k);
            ull w1 = ldp(swp + SW2_STRIDE + k);
            ull w2v = ldp(swp + 2 * SW2_STRIDE + k);
            ull w3 = ldp(swp + 3 * SW2_STRIDE + k);
            fma2(a00, w0, x0);  fma2(a01, w0, x1);  fma2(a02, w0, x2);  fma2(a03, w0, x3);
            fma2(a10, w1, x0);  fma2(a11, w1, x1);  fma2(a12, w1, x2);  fma2(a13, w1, x3);
            fma2(a20, w2v, x0); fma2(a21, w2v, x1); fma2(a22, w2v, x2); fma2(a23, w2v, x3);
            fma2(a30, w3, x0);  fma2(a31, w3, x1);  fma2(a32, w3, x2);  fma2(a33, w3, x3);
        }
    }

    float acc[4][4] = {
        {red2(a00),red2(a01),red2(a02),red2(a03)},
        {red2(a10),red2(a11),red2(a12),red2(a13)},
        {red2(a20),red2(a21),red2(a22),red2(a23)},
        {red2(a30),red2(a31),red2(a32),red2(a33)}};
    #pragma unroll
    for (int i = 0; i < 4; i++) {
        float bv = c2b[co0 + i];
        #pragma unroll
        for (int j = 0; j < 4; j++) {
            int t = t0 + j;
            if (t < T_) g_y2[(b * NF + co0 + i) * T_ + t] = acc[i][j] + bv;
        }
    }
}

// ======================================================================
// K5: hoisted input projection + LN1 (one warp per (b,t)).
// ======================================================================
__device__ __forceinline__ float warp_sum32(float v) {
    #pragma unroll
    for (int off = 16; off > 0; off >>= 1) v += __shfl_xor_sync(0xffffffffu, v, off);
    return v;
}

__global__ __launch_bounds__(256, 4)
void xt_kernel(const float* __restrict__ Wi, const float* __restrict__ bi,
               const float* __restrict__ ln1g, const float* __restrict__ ln1b) {
    __shared__ float sWi[32 * 33];
    __shared__ float sg[32], sb[32], sbi[32];
    const int tid = threadIdx.x;
    for (int i = tid; i < 32 * 32; i += 256) sWi[(i >> 5) * 33 + (i & 31)] = Wi[i];
    if (tid < 32) { sg[tid] = ln1g[tid]; sb[tid] = ln1b[tid]; sbi[tid] = bi[tid]; }
    __syncthreads();

    const int lane = tid & 31, wp = tid >> 5;
    const int p = blockIdx.x * 8 + wp;
    if (p >= B_ * T_) return;
    const int b = p / T_, t = p % T_;

    float f = g_y2[(b * NF + lane) * T_ + t];
    f = fmaxf(g_scale2[lane] * f + g_shift2[lane], 0.f);

    float acc = sbi[lane];
    #pragma unroll
    for (int j = 0; j < 32; j++) {
        float fj = __shfl_sync(0xffffffffu, f, j);
        acc += sWi[lane * 33 + j] * fj;
    }
    float m = warp_sum32(acc) * (1.f / 32.f);
    float d = acc - m;
    float v = warp_sum32(d * d) * (1.f / 32.f);
    float o = d * rsqrtf(v + EPSC) * sg[lane] + sb[lane];
    g_xt[(b * T_ + t) * LAT + lane] = o;
}

// ======================================================================
// K6: recurrent scan + mean pool + out proj (one 64-thread block per b).
// ======================================================================
__global__ __launch_bounds__(64, 8)
void rnn_kernel(const float* __restrict__ Wh, const float* __restrict__ bh,
                const float* __restrict__ ln2g, const float* __restrict__ ln2b,
                const float* __restrict__ Wr, const float* __restrict__ br,
                const float* __restrict__ Wo, const float* __restrict__ bo,
                float* __restrict__ out) {
    __shared__ float sWh[HID * 33];
    __shared__ float sWr[LAT * 65];
    __shared__ float sWo[LAT * 33];
    __shared__ float sbh[HID], sg[HID], sb2[HID], sbr[LAT], sbo[LAT];
    __shared__ float comb[LAT], hp[HID], hstate[LAT], pooled[LAT];
    __shared__ float red[4];

    const int tid = threadIdx.x;    // 64
    const int b   = blockIdx.x;

    for (int i = tid; i < HID * LAT; i += 64) sWh[(i >> 5) * 33 + (i & 31)] = Wh[i];
    for (int i = tid; i < LAT * HID; i += 64) sWr[(i >> 6) * 65 + (i & 63)] = Wr[i];
    for (int i = tid; i < LAT * LAT; i += 64) sWo[(i >> 5) * 33 + (i & 31)] = Wo[i];
    sbh[tid] = bh[tid]; sg[tid] = ln2g[tid]; sb2[tid] = ln2b[tid];
    if (tid < LAT) { sbr[tid] = br[tid]; sbo[tid] = bo[tid];
                     hstate[tid] = 0.f; pooled[tid] = 0.f; }
    __syncthreads();

    const float* xtb = g_xt + b * T_ * LAT;
    for (int t = 0; t < T_; t++) {
        if (tid < LAT) comb[tid] = xtb[t * LAT + tid] + hstate[tid];
        __syncthreads();

        float a = sbh[tid];
        #pragma unroll
        for (int k = 0; k < LAT; k++) a += sWh[tid * 33 + k] * comb[k];
        a = fmaxf(a, 0.f);

        float s = a, sq = a * a;
        #pragma unroll
        for (int off = 16; off > 0; off >>= 1) {
            s  += __shfl_xor_sync(0xffffffffu, s, off);
            sq += __shfl_xor_sync(0xffffffffu, sq, off);
        }
        if ((tid & 31) == 0) { red[tid >> 5] = s; red[2 + (tid >> 5)] = sq; }
        __syncthreads();
        float m = (red[0] + red[1]) * (1.f / 64.f);
        float v = (red[2] + red[3]) * (1.f / 64.f) - m * m;
        hp[tid] = (a - m) * rsqrtf(v + EPSC) * sg[tid] + sb2[tid];
        __syncthreads();

        if (tid < LAT) {
            float r = sbr[tid];
            #pragma unroll
            for (int k = 0; k < HID; k++) r += sWr[tid * 65 + k] * hp[k];
            float hn = tanhf(r);
            hstate[tid] = hn;
            pooled[tid] += hn;
        }
        __syncthreads();
    }

    if (tid < LAT) {
        float o = sbo[tid];
        const float invT = 1.f / (float)T_;
        #pragma unroll
        for (int k = 0; k < LAT; k++) o += sWo[tid * 33 + k] * (pooled[k] * invT);
        out[b * LAT + tid] = o;
    }
}

// ======================================================================
// launch
// ======================================================================
extern "C" void kernel_launch(void* const* d_in, const int* in_sizes, int n_in,
                              void* d_out, int out_size) {
    const float* x    = (const float*)d_in[0];
    const float* c1w  = (const float*)d_in[1];
    const float* c1b  = (const float*)d_in[2];
    const float* bn1g = (const float*)d_in[3];
    const float* bn1b = (const float*)d_in[4];
    const float* c2w  = (const float*)d_in[5];
    const float* c2b  = (const float*)d_in[6];
    const float* bn2g = (const float*)d_in[7];
    const float* bn2b = (const float*)d_in[8];
    const float* Wi   = (const float*)d_in[9];
    const float* bi   = (const float*)d_in[10];
    const float* ln1g = (const float*)d_in[11];
    const float* ln1b = (const float*)d_in[12];
    const float* Wh   = (const float*)d_in[13];
    const float* bh   = (const float*)d_in[14];
    const float* ln2g = (const float*)d_in[15];
    const float* ln2b = (const float*)d_in[16];
    const float* Wr   = (const float*)d_in[17];
    const float* br   = (const float*)d_in[18];
    const float* Wo   = (const float*)d_in[19];
    const float* bo   = (const float*)d_in[20];
    float* out = (float*)d_out;

    const int smem1 = (CIN * SX_STRIDE + CO1 * SW1_STRIDE) * 4;   // ~135.4 KB
    const int smem2 = (NF * SH_STRIDE + NF * SW2_STRIDE) * 4;     // ~166.5 KB
    cudaFuncSetAttribute(conv1_kernel, cudaFuncAttributeMaxDynamicSharedMemorySize, smem1);
    cudaFuncSetAttribute(conv2_kernel, cudaFuncAttributeMaxDynamicSharedMemorySize, smem2);

    conv1_kernel<<<B_ * 4, 256, smem1>>>(x, c1w, c1b);
    bn_stats_kernel<<<dim3(32, 16), 256>>>(0);
    bn_final_kernel<<<1, 32>>>(bn1g, bn1b, 0);
    conv2_kernel<<<B_, 256, smem2>>>(c2w, c2b);
    bn_stats_kernel<<<dim3(32, 16), 256>>>(1);
    bn_final_kernel<<<1, 32>>>(bn2g, bn2b, 1);
    xt_kernel<<<(B_ * T_ + 7) / 8, 256>>>(Wi, bi, ln1g, ln1b);
    rnn_kernel<<<B_, 64>>>(Wh, bh, ln2g, ln2b, Wr, br, Wo, bo, out);
}

// round 13
// speedup vs baseline: 1.1385x; 1.1385x over previous
#include <cuda_runtime.h>
#include <math.h>

// ---------------- problem constants ----------------
#define B_    512
#define CIN   12
#define LIN   5000
#define CO1   32
#define KS1   50
#define ST1   10
#define L1    496      // (5000-50)/10+1
#define NF    32
#define KS2   25
#define ST2   5
#define T_    95       // (496-25)/5+1
#define LAT   32
#define HID   64
#define EPSC  1e-5f

// ---------------- scratch (device globals; no allocation allowed) ----------------
__device__ float g_y1[B_ * CO1 * L1];   // conv1 output [b][co][l]
__device__ float g_y2[B_ * NF * T_];    // conv2 output [b][co][t]
__device__ float g_xt[B_ * T_ * LAT];   // hoisted LN(proj) [b][t][l]
__device__ float g_part[2][32][16];     // [sum|sumsq][ch][chunk]
__device__ float g_scale1[32], g_shift1[32];
__device__ float g_scale2[32], g_shift2[32];

// ======================================================================
// K1: conv1 + bias.  Block = (b, 124-wide l chunk), 512 threads (16 warps).
// Thread tile 4co x 2l (496 active).  Scalar FFMA (R6 math, occupancy 2x).
// ======================================================================
#define LBLK 124
#define SX_STRIDE 1284     // 1280 + 4 pad
#define SW1_STRIDE 601     // 600 + 1 pad (conflict-free weight rows)

__global__ __launch_bounds__(512, 1)
void conv1_kernel(const float* __restrict__ x, const float* __restrict__ w,
                  const float* __restrict__ bias) {
    extern __shared__ float smem[];
    float* sx = smem;                        // CIN * SX_STRIDE
    float* sw = smem + CIN * SX_STRIDE;      // CO1 * SW1_STRIDE

    const int b     = blockIdx.x >> 2;
    const int chunk = blockIdx.x & 3;
    const int l0    = chunk * LBLK;
    const int tid   = threadIdx.x;

    for (int i = tid; i < CO1 * CIN * KS1; i += 512) {
        int co = i / (CIN * KS1), r = i % (CIN * KS1);
        sw[co * SW1_STRIDE + r] = w[i];
    }
    const int xbase = b * CIN * LIN + l0 * ST1;
    for (int i = tid; i < CIN * 1280; i += 512) {
        int ci = i / 1280, p = i % 1280;
        sx[ci * SX_STRIDE + p] = x[xbase + ci * LIN + p];
    }
    __syncthreads();

    if (tid >= 496) return;                  // 8 co-grp * 62 l-grp
    const int co0 = (tid & 7) * 4;
    const int lt  = (tid >> 3) * 2;          // 0..122

    float a00=0,a01=0, a10=0,a11=0, a20=0,a21=0, a30=0,a31=0;

    for (int ci = 0; ci < CIN; ci++) {
        const float* sxp = sx + ci * SX_STRIDE + lt * ST1;
        const float* swp = sw + co0 * SW1_STRIDE + ci * KS1;
        #pragma unroll 10
        for (int k = 0; k < KS1; k++) {
            float x0 = sxp[k], x1 = sxp[k + 10];
            float w0 = swp[k];
            float w1 = swp[SW1_STRIDE + k];
            float w2 = swp[2 * SW1_STRIDE + k];
            float w3 = swp[3 * SW1_STRIDE + k];
            a00 += w0 * x0; a01 += w0 * x1;
            a10 += w1 * x0; a11 += w1 * x1;
            a20 += w2 * x0; a21 += w2 * x1;
            a30 += w3 * x0; a31 += w3 * x1;
        }
    }

    float* yp = g_y1 + (b * CO1 + co0) * L1 + l0 + lt;
    float b0 = bias[co0], b1 = bias[co0+1], b2 = bias[co0+2], b3 = bias[co0+3];
    yp[0] = a00 + b0; yp[1] = a01 + b0;  yp += L1;
    yp[0] = a10 + b1; yp[1] = a11 + b1;  yp += L1;
    yp[0] = a20 + b2; yp[1] = a21 + b2;  yp += L1;
    yp[0] = a30 + b3; yp[1] = a31 + b3;
}

// ======================================================================
// BN stats: deterministic two-pass tree reduction (no float atomics).
// ======================================================================
__global__ __launch_bounds__(256, 4)
void bn_stats_kernel(int which) {
    const float* y  = which ? g_y2 : g_y1;
    const int perB  = which ? T_ : L1;
    const int ch    = blockIdx.x;
    const int chunk = blockIdx.y;
    const int b0    = chunk * 32;
    const int tid   = threadIdx.x;
    const int n     = 32 * perB;

    float s = 0.f, sq = 0.f;
    for (int i = tid; i < n; i += 256) {
        int b = b0 + i / perB, p = i % perB;
        float v = y[(b * 32 + ch) * perB + p];
        s += v; sq += v * v;
    }
    __shared__ float rs[256], rq[256];
    rs[tid] = s; rq[tid] = sq;
    __syncthreads();
    for (int off = 128; off > 0; off >>= 1) {
        if (tid < off) { rs[tid] += rs[tid + off]; rq[tid] += rq[tid + off]; }
        __syncthreads();
    }
    if (tid == 0) {
        g_part[0][ch][chunk] = rs[0];
        g_part[1][ch][chunk] = rq[0];
    }
}

__global__ void bn_final_kernel(const float* __restrict__ g, const float* __restrict__ bb,
                                int which) {
    int ch = threadIdx.x;   // 32 threads
    float invN = which ? (1.f / (B_ * (float)T_)) : (1.f / (B_ * (float)L1));
    float s = 0.f, sq = 0.f;
    for (int c = 0; c < 16; c++) { s += g_part[0][ch][c]; sq += g_part[1][ch][c]; }
    float m  = s * invN;
    float v  = sq * invN - m * m;
    float sc = g[ch] * rsqrtf(v + EPSC);
    if (which) { g_scale2[ch] = sc; g_shift2[ch] = bb[ch] - m * sc; }
    else       { g_scale1[ch] = sc; g_shift1[ch] = bb[ch] - m * sc; }
}

// ======================================================================
// K3: conv2 + bias, BN1 affine + ReLU fused on input.  512 threads.
// Thread tile 2co x 3t (all 512 active; t=95 tail computed, discarded).
// SH_STRIDE 500 keeps the 3t window reads inside each row.
// ======================================================================
#define SH_STRIDE  500     // 496 + 4 pad (covers t0*5+10+24 = 499)
#define SW2_STRIDE 801     // 800 + 1 pad

__global__ __launch_bounds__(512, 1)
void conv2_kernel(const float* __restrict__ w2, const float* __restrict__ c2b) {
    extern __shared__ float smem[];
    float* sh = smem;                       // NF * SH_STRIDE
    float* sw = smem + NF * SH_STRIDE;      // NF * SW2_STRIDE

    const int b   = blockIdx.x;
    const int tid = threadIdx.x;

    for (int i = tid; i < NF * NF * KS2; i += 512) {   // 25600
        int co = i / (NF * KS2), r = i % (NF * KS2);
        sw[co * SW2_STRIDE + r] = w2[i];
    }
    for (int i = tid; i < NF * L1; i += 512) {
        int ci = i / L1, p = i % L1;
        float v = g_scale1[ci] * g_y1[(b * NF) * L1 + i] + g_shift1[ci];
        sh[ci * SH_STRIDE + p] = fmaxf(v, 0.f);
    }
    // zero the row pads so tail-tile reads are defined (values discarded anyway)
    for (int i = tid; i < NF * 4; i += 512) {
        sh[(i >> 2) * SH_STRIDE + L1 + (i & 3)] = 0.f;
    }
    __syncthreads();

    const int co0 = (tid & 15) * 2;          // 16 co-groups of 2
    const int t0  = (tid >> 4) * 3;          // 32 t-groups of 3 (covers 96)

    float a00=0,a01=0,a02=0, a10=0,a11=0,a12=0;

    for (int ci = 0; ci < NF; ci++) {
        const float* shp = sh + ci * SH_STRIDE + t0 * ST2;
        const float* swp = sw + co0 * SW2_STRIDE + ci * KS2;
        #pragma unroll 5
        for (int k = 0; k < KS2; k++) {
            float x0 = shp[k], x1 = shp[k + 5], x2 = shp[k + 10];
            float w0 = swp[k];
            float w1 = swp[SW2_STRIDE + k];
            a00 += w0 * x0; a01 += w0 * x1; a02 += w0 * x2;
            a10 += w1 * x0; a11 += w1 * x1; a12 += w1 * x2;
        }
    }

    float acc[2][3] = {{a00,a01,a02},{a10,a11,a12}};
    #pragma unroll
    for (int i = 0; i < 2; i++) {
        float bv = c2b[co0 + i];
        #pragma unroll
        for (int j = 0; j < 3; j++) {
            int t = t0 + j;
            if (t < T_) g_y2[(b * NF + co0 + i) * T_ + t] = acc[i][j] + bv;
        }
    }
}

// ======================================================================
// K5: hoisted input projection + LN1 (one warp per (b,t)).
// ======================================================================
__device__ __forceinline__ float warp_sum32(float v) {
    #pragma unroll
    for (int off = 16; off > 0; off >>= 1) v += __shfl_xor_sync(0xffffffffu, v, off);
    return v;
}

__global__ __launch_bounds__(256, 4)
void xt_kernel(const float* __restrict__ Wi, const float* __restrict__ bi,
               const float* __restrict__ ln1g, const float* __restrict__ ln1b) {
    __shared__ float sWi[32 * 33];
    __shared__ float sg[32], sb[32], sbi[32];
    const int tid = threadIdx.x;
    for (int i = tid; i < 32 * 32; i += 256) sWi[(i >> 5) * 33 + (i & 31)] = Wi[i];
    if (tid < 32) { sg[tid] = ln1g[tid]; sb[tid] = ln1b[tid]; sbi[tid] = bi[tid]; }
    __syncthreads();

    const int lane = tid & 31, wp = tid >> 5;
    const int p = blockIdx.x * 8 + wp;
    if (p >= B_ * T_) return;
    const int b = p / T_, t = p % T_;

    float f = g_y2[(b * NF + lane) * T_ + t];
    f = fmaxf(g_scale2[lane] * f + g_shift2[lane], 0.f);

    float acc = sbi[lane];
    #pragma unroll
    for (int j = 0; j < 32; j++) {
        float fj = __shfl_sync(0xffffffffu, f, j);
        acc += sWi[lane * 33 + j] * fj;
    }
    float m = warp_sum32(acc) * (1.f / 32.f);
    float d = acc - m;
    float v = warp_sum32(d * d) * (1.f / 32.f);
    float o = d * rsqrtf(v + EPSC) * sg[lane] + sb[lane];
    g_xt[(b * T_ + t) * LAT + lane] = o;
}

// ======================================================================
// K6: recurrent scan + mean pool + out proj (one 64-thread block per b).
// ======================================================================
__global__ __launch_bounds__(64, 8)
void rnn_kernel(const float* __restrict__ Wh, const float* __restrict__ bh,
                const float* __restrict__ ln2g, const float* __restrict__ ln2b,
                const float* __restrict__ Wr, const float* __restrict__ br,
                const float* __restrict__ Wo, const float* __restrict__ bo,
                float* __restrict__ out) {
    __shared__ float sWh[HID * 33];
    __shared__ float sWr[LAT * 65];
    __shared__ float sWo[LAT * 33];
    __shared__ float sbh[HID], sg[HID], sb2[HID], sbr[LAT], sbo[LAT];
    __shared__ float comb[LAT], hp[HID], hstate[LAT], pooled[LAT];
    __shared__ float red[4];

    const int tid = threadIdx.x;    // 64
    const int b   = blockIdx.x;

    for (int i = tid; i < HID * LAT; i += 64) sWh[(i >> 5) * 33 + (i & 31)] = Wh[i];
    for (int i = tid; i < LAT * HID; i += 64) sWr[(i >> 6) * 65 + (i & 63)] = Wr[i];
    for (int i = tid; i < LAT * LAT; i += 64) sWo[(i >> 5) * 33 + (i & 31)] = Wo[i];
    sbh[tid] = bh[tid]; sg[tid] = ln2g[tid]; sb2[tid] = ln2b[tid];
    if (tid < LAT) { sbr[tid] = br[tid]; sbo[tid] = bo[tid];
                     hstate[tid] = 0.f; pooled[tid] = 0.f; }
    __syncthreads();

    const float* xtb = g_xt + b * T_ * LAT;
    for (int t = 0; t < T_; t++) {
        if (tid < LAT) comb[tid] = xtb[t * LAT + tid] + hstate[tid];
        __syncthreads();

        float a = sbh[tid];
        #pragma unroll
        for (int k = 0; k < LAT; k++) a += sWh[tid * 33 + k] * comb[k];
        a = fmaxf(a, 0.f);

        float s = a, sq = a * a;
        #pragma unroll
        for (int off = 16; off > 0; off >>= 1) {
            s  += __shfl_xor_sync(0xffffffffu, s, off);
            sq += __shfl_xor_sync(0xffffffffu, sq, off);
        }
        if ((tid & 31) == 0) { red[tid >> 5] = s; red[2 + (tid >> 5)] = sq; }
        __syncthreads();
        float m = (red[0] + red[1]) * (1.f / 64.f);
        float v = (red[2] + red[3]) * (1.f / 64.f) - m * m;
        hp[tid] = (a - m) * rsqrtf(v + EPSC) * sg[tid] + sb2[tid];
        __syncthreads();

        if (tid < LAT) {
            float r = sbr[tid];
            #pragma unroll
            for (int k = 0; k < HID; k++) r += sWr[tid * 65 + k] * hp[k];
            float hn = tanhf(r);
            hstate[tid] = hn;
            pooled[tid] += hn;
        }
        __syncthreads();
    }

    if (tid < LAT) {
        float o = sbo[tid];
        const float invT = 1.f / (float)T_;
        #pragma unroll
        for (int k = 0; k < LAT; k++) o += sWo[tid * 33 + k] * (pooled[k] * invT);
        out[b * LAT + tid] = o;
    }
}

// ======================================================================
// launch
// ======================================================================
extern "C" void kernel_launch(void* const* d_in, const int* in_sizes, int n_in,
                              void* d_out, int out_size) {
    const float* x    = (const float*)d_in[0];
    const float* c1w  = (const float*)d_in[1];
    const float* c1b  = (const float*)d_in[2];
    const float* bn1g = (const float*)d_in[3];
    const float* bn1b = (const float*)d_in[4];
    const float* c2w  = (const float*)d_in[5];
    const float* c2b  = (const float*)d_in[6];
    const float* bn2g = (const float*)d_in[7];
    const float* bn2b = (const float*)d_in[8];
    const float* Wi   = (const float*)d_in[9];
    const float* bi   = (const float*)d_in[10];
    const float* ln1g = (const float*)d_in[11];
    const float* ln1b = (const float*)d_in[12];
    const float* Wh   = (const float*)d_in[13];
    const float* bh   = (const float*)d_in[14];
    const float* ln2g = (const float*)d_in[15];
    const float* ln2b = (const float*)d_in[16];
    const float* Wr   = (const float*)d_in[17];
    const float* br   = (const float*)d_in[18];
    const float* Wo   = (const float*)d_in[19];
    const float* bo   = (const float*)d_in[20];
    float* out = (float*)d_out;

    const int smem1 = (CIN * SX_STRIDE + CO1 * SW1_STRIDE) * 4;   // ~135.3 KB
    const int smem2 = (NF * SH_STRIDE + NF * SW2_STRIDE) * 4;     // ~162.6 KB
    cudaFuncSetAttribute(conv1_kernel, cudaFuncAttributeMaxDynamicSharedMemorySize, smem1);
    cudaFuncSetAttribute(conv2_kernel, cudaFuncAttributeMaxDynamicSharedMemorySize, smem2);

    conv1_kernel<<<B_ * 4, 512, smem1>>>(x, c1w, c1b);
    bn_stats_kernel<<<dim3(32, 16), 256>>>(0);
    bn_final_kernel<<<1, 32>>>(bn1g, bn1b, 0);
    conv2_kernel<<<B_, 512, smem2>>>(c2w, c2b);
    bn_stats_kernel<<<dim3(32, 16), 256>>>(1);
    bn_final_kernel<<<1, 32>>>(bn2g, bn2b, 1);
    xt_kernel<<<(B_ * T_ + 7) / 8, 256>>>(Wi, bi, ln1g, ln1b);
    rnn_kernel<<<B_, 64>>>(Wh, bh, ln2g, ln2b, Wr, br, Wo, bo, out);
}

// round 15
// speedup vs baseline: 1.2946x; 1.1371x over previous
#include <cuda_runtime.h>
#include <math.h>

// ---------------- problem constants ----------------
#define B_    512
#define CIN   12
#define LIN   5000
#define CO1   32
#define KS1   50
#define ST1   10
#define L1    496      // (5000-50)/10+1
#define NF    32
#define KS2   25
#define ST2   5
#define T_    95       // (496-25)/5+1
#define LAT   32
#define HID   64
#define EPSC  1e-5f

// ---------------- scratch (device globals; no allocation allowed) ----------------
__device__ float g_y1[B_ * CO1 * L1];   // conv1 output [b][co][l]
__device__ float g_y2[B_ * NF * T_];    // conv2 output [b][co][t]
__device__ float g_xt[B_ * T_ * LAT];   // hoisted LN(proj) [b][t][l]
__device__ float g_part[2][32][16];     // [sum|sumsq][ch][chunk]
__device__ float g_scale1[32], g_shift1[32];
__device__ float g_scale2[32], g_shift2[32];

// ======================================================================
// K1: conv1 + bias.  Block = (b, 248-wide l chunk), 512 threads (16 warps).
// Thread tile 4co x 4l (496 active): 16 FMA per 8 LDS, 4 warps/SMSP.
// smem: x 12 x 2524, w 32 x 601 (~193 KB, 1 CTA/SM by design).
// ======================================================================
#define LBLK 248
#define SX_STRIDE 2524     // 248*10+40 = 2520, +4 pad
#define SW1_STRIDE 601     // 600 + 1 pad (conflict-free weight rows)

__global__ __launch_bounds__(512, 1)
void conv1_kernel(const float* __restrict__ x, const float* __restrict__ w,
                  const float* __restrict__ bias) {
    extern __shared__ float smem[];
    float* sx = smem;                        // CIN * SX_STRIDE
    float* sw = smem + CIN * SX_STRIDE;      // CO1 * SW1_STRIDE

    const int b     = blockIdx.x >> 1;
    const int chunk = blockIdx.x & 1;
    const int l0    = chunk * LBLK;
    const int tid   = threadIdx.x;

    for (int i = tid; i < CO1 * CIN * KS1; i += 512) {
        int co = i / (CIN * KS1), r = i % (CIN * KS1);
        sw[co * SW1_STRIDE + r] = w[i];
    }
    // x segment: positions [l0*10, l0*10+2520) per channel (exactly in-bounds:
    // chunk 1 -> 2480..5000)
    const int xbase = b * CIN * LIN + l0 * ST1;
    for (int i = tid; i < CIN * 2520; i += 512) {
        int ci = i / 2520, p = i % 2520;
        sx[ci * SX_STRIDE + p] = x[xbase + ci * LIN + p];
    }
    __syncthreads();

    if (tid >= 496) return;                  // 8 co-grp * 62 l-grp
    const int co0 = (tid & 7) * 4;
    const int lt  = (tid >> 3) * 4;          // 0..244

    float a00=0,a01=0,a02=0,a03=0, a10=0,a11=0,a12=0,a13=0;
    float a20=0,a21=0,a22=0,a23=0, a30=0,a31=0,a32=0,a33=0;

    for (int ci = 0; ci < CIN; ci++) {
        const float* sxp = sx + ci * SX_STRIDE + lt * ST1;
        const float* swp = sw + co0 * SW1_STRIDE + ci * KS1;
        #pragma unroll 10
        for (int k = 0; k < KS1; k++) {
            float x0 = sxp[k], x1 = sxp[k + 10], x2 = sxp[k + 20], x3 = sxp[k + 30];
            float w0 = swp[k];
            float w1 = swp[SW1_STRIDE + k];
            float w2 = swp[2 * SW1_STRIDE + k];
            float w3 = swp[3 * SW1_STRIDE + k];
            a00 += w0 * x0; a01 += w0 * x1; a02 += w0 * x2; a03 += w0 * x3;
            a10 += w1 * x0; a11 += w1 * x1; a12 += w1 * x2; a13 += w1 * x3;
            a20 += w2 * x0; a21 += w2 * x1; a22 += w2 * x2; a23 += w2 * x3;
            a30 += w3 * x0; a31 += w3 * x1; a32 += w3 * x2; a33 += w3 * x3;
        }
    }

    float* yp = g_y1 + (b * CO1 + co0) * L1 + l0 + lt;
    float b0 = bias[co0], b1 = bias[co0+1], b2 = bias[co0+2], b3 = bias[co0+3];
    yp[0] = a00+b0; yp[1] = a01+b0; yp[2] = a02+b0; yp[3] = a03+b0;  yp += L1;
    yp[0] = a10+b1; yp[1] = a11+b1; yp[2] = a12+b1; yp[3] = a13+b1;  yp += L1;
    yp[0] = a20+b2; yp[1] = a21+b2; yp[2] = a22+b2; yp[3] = a23+b2;  yp += L1;
    yp[0] = a30+b3; yp[1] = a31+b3; yp[2] = a32+b3; yp[3] = a33+b3;
}

// ======================================================================
// BN stats: deterministic two-pass tree reduction (no float atomics).
// ======================================================================
__global__ __launch_bounds__(256, 4)
void bn_stats_kernel(int which) {
    const float* y  = which ? g_y2 : g_y1;
    const int perB  = which ? T_ : L1;
    const int ch    = blockIdx.x;
    const int chunk = blockIdx.y;
    const int b0    = chunk * 32;
    const int tid   = threadIdx.x;
    const int n     = 32 * perB;

    float s = 0.f, sq = 0.f;
    for (int i = tid; i < n; i += 256) {
        int b = b0 + i / perB, p = i % perB;
        float v = y[(b * 32 + ch) * perB + p];
        s += v; sq += v * v;
    }
    __shared__ float rs[256], rq[256];
    rs[tid] = s; rq[tid] = sq;
    __syncthreads();
    for (int off = 128; off > 0; off >>= 1) {
        if (tid < off) { rs[tid] += rs[tid + off]; rq[tid] += rq[tid + off]; }
        __syncthreads();
    }
    if (tid == 0) {
        g_part[0][ch][chunk] = rs[0];
        g_part[1][ch][chunk] = rq[0];
    }
}

__global__ void bn_final_kernel(const float* __restrict__ g, const float* __restrict__ bb,
                                int which) {
    int ch = threadIdx.x;   // 32 threads
    float invN = which ? (1.f / (B_ * (float)T_)) : (1.f / (B_ * (float)L1));
    float s = 0.f, sq = 0.f;
    for (int c = 0; c < 16; c++) { s += g_part[0][ch][c]; sq += g_part[1][ch][c]; }
    float m  = s * invN;
    float v  = sq * invN - m * m;
    float sc = g[ch] * rsqrtf(v + EPSC);
    if (which) { g_scale2[ch] = sc; g_shift2[ch] = bb[ch] - m * sc; }
    else       { g_scale1[ch] = sc; g_shift1[ch] = bb[ch] - m * sc; }
}

// ======================================================================
// K3: conv2 + bias, BN1 affine + ReLU fused on input.  512 threads.
// Thread tile 2co x 3t (all 512 active; t=95 tail computed, discarded).
// (R13-measured 139.5 us; unchanged this round.)
// ======================================================================
#define SH_STRIDE  500     // 496 + 4 pad (covers t0*5+10+24 = 499)
#define SW2_STRIDE 801     // 800 + 1 pad

__global__ __launch_bounds__(512, 1)
void conv2_kernel(const float* __restrict__ w2, const float* __restrict__ c2b) {
    extern __shared__ float smem[];
    float* sh = smem;                       // NF * SH_STRIDE
    float* sw = smem + NF * SH_STRIDE;      // NF * SW2_STRIDE

    const int b   = blockIdx.x;
    const int tid = threadIdx.x;

    for (int i = tid; i < NF * NF * KS2; i += 512) {   // 25600
        int co = i / (NF * KS2), r = i % (NF * KS2);
        sw[co * SW2_STRIDE + r] = w2[i];
    }
    for (int i = tid; i < NF * L1; i += 512) {
        int ci = i / L1, p = i % L1;
        float v = g_scale1[ci] * g_y1[(b * NF) * L1 + i] + g_shift1[ci];
        sh[ci * SH_STRIDE + p] = fmaxf(v, 0.f);
    }
    // zero the row pads so tail-tile reads are defined (values discarded anyway)
    for (int i = tid; i < NF * 4; i += 512) {
        sh[(i >> 2) * SH_STRIDE + L1 + (i & 3)] = 0.f;
    }
    __syncthreads();

    const int co0 = (tid & 15) * 2;          // 16 co-groups of 2
    const int t0  = (tid >> 4) * 3;          // 32 t-groups of 3 (covers 96)

    float a00=0,a01=0,a02=0, a10=0,a11=0,a12=0;

    for (int ci = 0; ci < NF; ci++) {
        const float* shp = sh + ci * SH_STRIDE + t0 * ST2;
        const float* swp = sw + co0 * SW2_STRIDE + ci * KS2;
        #pragma unroll 5
        for (int k = 0; k < KS2; k++) {
            float x0 = shp[k], x1 = shp[k + 5], x2 = shp[k + 10];
            float w0 = swp[k];
            float w1 = swp[SW2_STRIDE + k];
            a00 += w0 * x0; a01 += w0 * x1; a02 += w0 * x2;
            a10 += w1 * x0; a11 += w1 * x1; a12 += w1 * x2;
        }
    }

    float acc[2][3] = {{a00,a01,a02},{a10,a11,a12}};
    #pragma unroll
    for (int i = 0; i < 2; i++) {
        float bv = c2b[co0 + i];
        #pragma unroll
        for (int j = 0; j < 3; j++) {
            int t = t0 + j;
            if (t < T_) g_y2[(b * NF + co0 + i) * T_ + t] = acc[i][j] + bv;
        }
    }
}

// ======================================================================
// K5: hoisted input projection + LN1 (one warp per (b,t)).
// ======================================================================
__device__ __forceinline__ float warp_sum32(float v) {
    #pragma unroll
    for (int off = 16; off > 0; off >>= 1) v += __shfl_xor_sync(0xffffffffu, v, off);
    return v;
}

__global__ __launch_bounds__(256, 4)
void xt_kernel(const float* __restrict__ Wi, const float* __restrict__ bi,
               const float* __restrict__ ln1g, const float* __restrict__ ln1b) {
    __shared__ float sWi[32 * 33];
    __shared__ float sg[32], sb[32], sbi[32];
    const int tid = threadIdx.x;
    for (int i = tid; i < 32 * 32; i += 256) sWi[(i >> 5) * 33 + (i & 31)] = Wi[i];
    if (tid < 32) { sg[tid] = ln1g[tid]; sb[tid] = ln1b[tid]; sbi[tid] = bi[tid]; }
    __syncthreads();

    const int lane = tid & 31, wp = tid >> 5;
    const int p = blockIdx.x * 8 + wp;
    if (p >= B_ * T_) return;
    const int b = p / T_, t = p % T_;

    float f = g_y2[(b * NF + lane) * T_ + t];
    f = fmaxf(g_scale2[lane] * f + g_shift2[lane], 0.f);

    float acc = sbi[lane];
    #pragma unroll
    for (int j = 0; j < 32; j++) {
        float fj = __shfl_sync(0xffffffffu, f, j);
        acc += sWi[lane * 33 + j] * fj;
    }
    float m = warp_sum32(acc) * (1.f / 32.f);
    float d = acc - m;
    float v = warp_sum32(d * d) * (1.f / 32.f);
    float o = d * rsqrtf(v + EPSC) * sg[lane] + sb[lane];
    g_xt[(b * T_ + t) * LAT + lane] = o;
}

// ======================================================================
// K6: recurrent scan + mean pool + out proj (one 64-thread block per b).
// ======================================================================
__global__ __launch_bounds__(64, 8)
void rnn_kernel(const float* __restrict__ Wh, const float* __restrict__ bh,
                const float* __restrict__ ln2g, const float* __restrict__ ln2b,
                const float* __restrict__ Wr, const float* __restrict__ br,
                const float* __restrict__ Wo, const float* __restrict__ bo,
                float* __restrict__ out) {
    __shared__ float sWh[HID * 33];
    __shared__ float sWr[LAT * 65];
    __shared__ float sWo[LAT * 33];
    __shared__ float sbh[HID], sg[HID], sb2[HID], sbr[LAT], sbo[LAT];
    __shared__ float comb[LAT], hp[HID], hstate[LAT], pooled[LAT];
    __shared__ float red[4];

    const int tid = threadIdx.x;    // 64
    const int b   = blockIdx.x;

    for (int i = tid; i < HID * LAT; i += 64) sWh[(i >> 5) * 33 + (i & 31)] = Wh[i];
    for (int i = tid; i < LAT * HID; i += 64) sWr[(i >> 6) * 65 + (i & 63)] = Wr[i];
    for (int i = tid; i < LAT * LAT; i += 64) sWo[(i >> 5) * 33 + (i & 31)] = Wo[i];
    sbh[tid] = bh[tid]; sg[tid] = ln2g[tid]; sb2[tid] = ln2b[tid];
    if (tid < LAT) { sbr[tid] = br[tid]; sbo[tid] = bo[tid];
                     hstate[tid] = 0.f; pooled[tid] = 0.f; }
    __syncthreads();

    const float* xtb = g_xt + b * T_ * LAT;
    for (int t = 0; t < T_; t++) {
        if (tid < LAT) comb[tid] = xtb[t * LAT + tid] + hstate[tid];
        __syncthreads();

        float a = sbh[tid];
        #pragma unroll
        for (int k = 0; k < LAT; k++) a += sWh[tid * 33 + k] * comb[k];
        a = fmaxf(a, 0.f);

        float s = a, sq = a * a;
        #pragma unroll
        for (int off = 16; off > 0; off >>= 1) {
            s  += __shfl_xor_sync(0xffffffffu, s, off);
            sq += __shfl_xor_sync(0xffffffffu, sq, off);
        }
        if ((tid & 31) == 0) { red[tid >> 5] = s; red[2 + (tid >> 5)] = sq; }
        __syncthreads();
        float m = (red[0] + red[1]) * (1.f / 64.f);
        float v = (red[2] + red[3]) * (1.f / 64.f) - m * m;
        hp[tid] = (a - m) * rsqrtf(v + EPSC) * sg[tid] + sb2[tid];
        __syncthreads();

        if (tid < LAT) {
            float r = sbr[tid];
            #pragma unroll
            for (int k = 0; k < HID; k++) r += sWr[tid * 65 + k] * hp[k];
            float hn = tanhf(r);
            hstate[tid] = hn;
            pooled[tid] += hn;
        }
        __syncthreads();
    }

    if (tid < LAT) {
        float o = sbo[tid];
        const float invT = 1.f / (float)T_;
        #pragma unroll
        for (int k = 0; k < LAT; k++) o += sWo[tid * 33 + k] * (pooled[k] * invT);
        out[b * LAT + tid] = o;
    }
}

// ======================================================================
// launch
// ======================================================================
extern "C" void kernel_launch(void* const* d_in, const int* in_sizes, int n_in,
                              void* d_out, int out_size) {
    const float* x    = (const float*)d_in[0];
    const float* c1w  = (const float*)d_in[1];
    const float* c1b  = (const float*)d_in[2];
    const float* bn1g = (const float*)d_in[3];
    const float* bn1b = (const float*)d_in[4];
    const float* c2w  = (const float*)d_in[5];
    const float* c2b  = (const float*)d_in[6];
    const float* bn2g = (const float*)d_in[7];
    const float* bn2b = (const float*)d_in[8];
    const float* Wi   = (const float*)d_in[9];
    const float* bi   = (const float*)d_in[10];
    const float* ln1g = (const float*)d_in[11];
    const float* ln1b = (const float*)d_in[12];
    const float* Wh   = (const float*)d_in[13];
    const float* bh   = (const float*)d_in[14];
    const float* ln2g = (const float*)d_in[15];
    const float* ln2b = (const float*)d_in[16];
    const float* Wr   = (const float*)d_in[17];
    const float* br   = (const float*)d_in[18];
    const float* Wo   = (const float*)d_in[19];
    const float* bo   = (const float*)d_in[20];
    float* out = (float*)d_out;

    const int smem1 = (CIN * SX_STRIDE + CO1 * SW1_STRIDE) * 4;   // ~193.4 KB
    const int smem2 = (NF * SH_STRIDE + NF * SW2_STRIDE) * 4;     // ~162.6 KB
    cudaFuncSetAttribute(conv1_kernel, cudaFuncAttributeMaxDynamicSharedMemorySize, smem1);
    cudaFuncSetAttribute(conv2_kernel, cudaFuncAttributeMaxDynamicSharedMemorySize, smem2);

    conv1_kernel<<<B_ * 2, 512, smem1>>>(x, c1w, c1b);
    bn_stats_kernel<<<dim3(32, 16), 256>>>(0);
    bn_final_kernel<<<1, 32>>>(bn1g, bn1b, 0);
    conv2_kernel<<<B_, 512, smem2>>>(c2w, c2b);
    bn_stats_kernel<<<dim3(32, 16), 256>>>(1);
    bn_final_kernel<<<1, 32>>>(bn2g, bn2b, 1);
    xt_kernel<<<(B_ * T_ + 7) / 8, 256>>>(Wi, bi, ln1g, ln1b);
    rnn_kernel<<<B_, 64>>>(Wh, bh, ln2g, ln2b, Wr, br, Wo, bo, out);
}